// round 1
// baseline (speedup 1.0000x reference)
#include <cuda_runtime.h>

// Problem constants
#define BB 32
#define CC 256
#define HH 32
#define WW 32
#define KK 1024
#define NN 1024                      // H*W
#define ZP_BATCH (CC * NN)           // 262144 floats per batch
#define ZQ_SIZE (BB * CC * HH * WW)  // 8388608
#define IDX_SIZE (BB * NN)           // 32768

// Device scratch (allocation-free rule: __device__ globals)
__device__ float g_zp[BB * ZP_BATCH];   // z permuted to [b][h][w][c] contiguous (= [b][256][1024] view)
__device__ float g_e2[KK];              // ||E_k||^2
__device__ float g_z2[BB * NN];         // column norms of the reinterpreted Z view
__device__ int   g_idx[BB * NN];        // argmin indices
__device__ float g_losspart[1024];      // per-block loss partials (deterministic reduce)

// ---------- packed f32x2 helpers (sm_100+ PTX) ----------
__device__ __forceinline__ unsigned long long pack2(float lo, float hi) {
    unsigned long long r;
    asm("mov.b64 %0, {%1, %2};" : "=l"(r) : "f"(lo), "f"(hi));
    return r;
}
__device__ __forceinline__ void unpack2(unsigned long long v, float& lo, float& hi) {
    asm("mov.b64 {%0, %1}, %2;" : "=f"(lo), "=f"(hi) : "l"(v));
}
__device__ __forceinline__ void fma2(unsigned long long& d, unsigned long long a, unsigned long long b) {
    asm("fma.rn.f32x2 %0, %1, %2, %0;" : "+l"(d) : "l"(a), "l"(b));
}

// ---------- kernel 1: e2[k] = sum_c E[k][c]^2 (warp per k) ----------
__global__ void k_e2(const float* __restrict__ E) {
    int warp = threadIdx.x >> 5, lane = threadIdx.x & 31;
    int k = blockIdx.x * 8 + warp;   // 128 blocks * 8 warps = 1024
    const float* row = E + k * CC;
    float s = 0.f;
#pragma unroll
    for (int i = 0; i < 8; i++) { float v = row[lane + 32 * i]; s = fmaf(v, v, s); }
#pragma unroll
    for (int o = 16; o; o >>= 1) s += __shfl_xor_sync(0xFFFFFFFFu, s, o);
    if (lane == 0) g_e2[k] = s;
}

// ---------- kernel 2: transpose z[b,c,h,w] -> g_zp[b][h][w][c] ----------
__global__ void k_tr(const float* __restrict__ z) {
    __shared__ float s[CC][33];       // padded: conflict-free both phases
    int b = blockIdx.x >> 5, h = blockIdx.x & 31;
    int w = threadIdx.x & 31, t8 = threadIdx.x >> 5;  // t8 in [0,8)
    const float* zp = z + ((long long)(b * CC) * HH + h) * WW + w;
#pragma unroll
    for (int i = 0; i < 32; i++) {
        int c = t8 * 32 + i;
        s[c][w] = zp[(long long)c * HH * WW];
    }
    __syncthreads();
    float* out = g_zp + (long long)b * ZP_BATCH + h * (WW * CC);
#pragma unroll
    for (int i = 0; i < 32; i++) {
        int f = threadIdx.x + i * 256;     // 0..8191 contiguous output
        int c = f & 255, ww = f >> 8;
        out[f] = s[c][ww];
    }
}

// ---------- kernel 3: z2[b][n] = sum_i M[i][n]^2 over the [256,1024] view ----------
__global__ void k_z2() {
    int b = blockIdx.x >> 2;                    // 128 blocks
    int n = (blockIdx.x & 3) * 256 + threadIdx.x;
    const float* base = g_zp + (long long)b * ZP_BATCH + n;
    float s = 0.f;
#pragma unroll 8
    for (int i = 0; i < CC; i++) { float v = base[i * NN]; s = fmaf(v, v, s); }
    g_z2[b * NN + n] = s;
}

// ---------- kernel 4: fused GEMM (f32x2) + argmin ----------
// dist[k][n] = (e2[k] + z2[n]) - 2 * sum_i E[k][i] * M[i][n]
// Block: 256 threads = (ty 16) x (tx 16). Tile: 128 k x 128 n, 8-deep c-chunks.
__global__ void __launch_bounds__(256) k_gemm(const float* __restrict__ E,
                                              float* __restrict__ dout, int out_size) {
    __shared__ float Es[2][8][128];   // [buf][c][k]  (transposed for contiguous a-frag)
    __shared__ float Ms[2][8][128];   // [buf][c][n]
    __shared__ float sval[16][128];
    __shared__ int   sidx[16][128];

    int tid = threadIdx.x;
    int ty = tid >> 4, tx = tid & 15;
    int b = blockIdx.x >> 3;
    int n0 = (blockIdx.x & 7) * 128;
    const float* Mb = g_zp + (long long)b * ZP_BATCH;

    float z2v[8];
#pragma unroll
    for (int j = 0; j < 8; j++) z2v[j] = g_z2[b * NN + n0 + tx * 8 + j];

    float best_v[8];
    int   best_k[8];
#pragma unroll
    for (int j = 0; j < 8; j++) { best_v[j] = 3.4e38f; best_k[j] = 0; }

    // load-role indices
    int ekk = tid >> 1;          // 0..127  (k within tile)
    int ec4 = (tid & 1) * 4;     // 0 or 4  (c within chunk)
    int mcc = tid >> 5;          // 0..7    (c within chunk)
    int mnn = (tid & 31) * 4;    // 0..124  (n within tile)

    for (int ko = 0; ko < 8; ko++) {
        int k0 = ko * 128;
        unsigned long long acc[8][4];
#pragma unroll
        for (int i = 0; i < 8; i++)
#pragma unroll
            for (int j = 0; j < 4; j++) acc[i][j] = 0ull;

        // prefetch chunk 0
        float4 ef = *(const float4*)&E[(k0 + ekk) * CC + ec4];
        float4 mf = *(const float4*)&Mb[mcc * NN + n0 + mnn];
        Es[0][ec4 + 0][ekk] = ef.x; Es[0][ec4 + 1][ekk] = ef.y;
        Es[0][ec4 + 2][ekk] = ef.z; Es[0][ec4 + 3][ekk] = ef.w;
        *(float4*)&Ms[0][mcc][mnn] = mf;
        __syncthreads();

        for (int ch = 0; ch < 32; ch++) {
            int cur = ch & 1;
            if (ch + 1 < 32) {
                int c0 = (ch + 1) * 8;
                ef = *(const float4*)&E[(k0 + ekk) * CC + c0 + ec4];
                mf = *(const float4*)&Mb[(c0 + mcc) * NN + n0 + mnn];
            }
#pragma unroll
            for (int cc = 0; cc < 8; cc++) {
                const unsigned long long* pb = (const unsigned long long*)&Ms[cur][cc][tx * 8];
                unsigned long long b0 = pb[0], b1 = pb[1], b2 = pb[2], b3 = pb[3];
                float4 af0 = *(const float4*)&Es[cur][cc][ty * 8];
                float4 af1 = *(const float4*)&Es[cur][cc][ty * 8 + 4];
                float a[8] = {af0.x, af0.y, af0.z, af0.w, af1.x, af1.y, af1.z, af1.w};
#pragma unroll
                for (int i = 0; i < 8; i++) {
                    unsigned long long ad = pack2(a[i], a[i]);
                    fma2(acc[i][0], ad, b0);
                    fma2(acc[i][1], ad, b1);
                    fma2(acc[i][2], ad, b2);
                    fma2(acc[i][3], ad, b3);
                }
            }
            if (ch + 1 < 32) {
                int nxt = cur ^ 1;
                Es[nxt][ec4 + 0][ekk] = ef.x; Es[nxt][ec4 + 1][ekk] = ef.y;
                Es[nxt][ec4 + 2][ekk] = ef.z; Es[nxt][ec4 + 3][ekk] = ef.w;
                *(float4*)&Ms[nxt][mcc][mnn] = mf;
            }
            __syncthreads();
        }

        // fold this k-slab into running argmin (first-min tie-break via k compare)
#pragma unroll
        for (int i = 0; i < 8; i++) {
            int kg = k0 + ty * 8 + i;
            float e2k = g_e2[kg];
#pragma unroll
            for (int j2 = 0; j2 < 4; j2++) {
                float d0, d1;
                unpack2(acc[i][j2], d0, d1);
                {
                    int j = j2 * 2;
                    float t = e2k + z2v[j];
                    float dist = t - 2.0f * d0;
                    if (dist < best_v[j] || (dist == best_v[j] && kg < best_k[j])) { best_v[j] = dist; best_k[j] = kg; }
                }
                {
                    int j = j2 * 2 + 1;
                    float t = e2k + z2v[j];
                    float dist = t - 2.0f * d1;
                    if (dist < best_v[j] || (dist == best_v[j] && kg < best_k[j])) { best_v[j] = dist; best_k[j] = kg; }
                }
            }
        }
    }

    // cross-ty reduction
    __syncthreads();
#pragma unroll
    for (int j = 0; j < 8; j++) {
        sval[ty][tx * 8 + j] = best_v[j];
        sidx[ty][tx * 8 + j] = best_k[j];
    }
    __syncthreads();
    if (tid < 128) {
        float bv = sval[0][tid];
        int bk = sidx[0][tid];
#pragma unroll
        for (int t = 1; t < 16; t++) {
            float v = sval[t][tid];
            int k2 = sidx[t][tid];
            if (v < bv || (v == bv && k2 < bk)) { bv = v; bk = k2; }
        }
        int n = n0 + tid;
        g_idx[b * NN + n] = bk;
        long long off = (long long)ZQ_SIZE + b * NN + n;
        if (off < (long long)out_size) dout[off] = (float)bk;
    }
}

// ---------- kernel 5: gather z_q, write output [b,c,h,w], loss partials ----------
__global__ void k_gather(const float* __restrict__ z, const float* __restrict__ E,
                         float* __restrict__ dout) {
    int b = blockIdx.x >> 5, h = blockIdx.x & 31;
    int w = threadIdx.x & 31, warp = threadIdx.x >> 5;
    int kidx = g_idx[b * NN + h * WW + w];
    const float* erow = E + kidx * CC;
    float local = 0.f;
#pragma unroll 4
    for (int s = 0; s < 32; s++) {
        int c = warp * 32 + s;
        long long zoff = ((long long)(b * CC + c) * HH + h) * WW + w;
        float zv = z[zoff];
        float eq = erow[c];
        float d = eq - zv;
        local = fmaf(d, d, local);
        dout[zoff] = eq;   // z_q_st == z_q numerically (straight-through)
    }
#pragma unroll
    for (int o = 16; o; o >>= 1) local += __shfl_xor_sync(0xFFFFFFFFu, local, o);
    __shared__ float sw[8];
    if ((threadIdx.x & 31) == 0) sw[warp] = local;
    __syncthreads();
    if (threadIdx.x == 0) {
        float s2 = 0.f;
#pragma unroll
        for (int i = 0; i < 8; i++) s2 += sw[i];
        g_losspart[blockIdx.x] = s2;
    }
}

// ---------- kernel 6: deterministic loss finalize ----------
__global__ void k_final(float* __restrict__ dout, int out_size) {
    __shared__ float sm[256];
    float s = 0.f;
    for (int i = threadIdx.x; i < 1024; i += 256) s += g_losspart[i];
    sm[threadIdx.x] = s;
    __syncthreads();
    if (threadIdx.x == 0) {
        float t = 0.f;
        for (int i = 0; i < 256; i++) t += sm[i];
        float m = t / 8388608.0f;                 // mean((z_q - z_p)^2)
        float loss = m + 0.25f * m;               // + BETA * same mean
        long long off = (long long)ZQ_SIZE + IDX_SIZE;
        if (off < (long long)out_size) dout[off] = loss;
    }
}

extern "C" void kernel_launch(void* const* d_in, const int* in_sizes, int n_in,
                              void* d_out, int out_size) {
    const float* z = (const float*)d_in[0];
    const float* E = (const float*)d_in[1];
    float* out = (float*)d_out;

    k_e2<<<128, 256>>>(E);
    k_tr<<<1024, 256>>>(z);
    k_z2<<<128, 256>>>();
    k_gemm<<<256, 256>>>(E, out, out_size);
    if (out_size >= ZQ_SIZE) k_gather<<<1024, 256>>>(z, E, out);
    k_final<<<1, 256>>>(out, out_size);
}